// round 9
// baseline (speedup 1.0000x reference)
#include <cuda_runtime.h>
#include <cuda_fp16.h>
#include <cstdint>

#define NB 32
#define CCH 512
#define AA 256
#define HWD 4096
#define PHW 1024

typedef unsigned int u32;
typedef unsigned short u16;

// ---------------- scratch (static device globals) ---------------------------
__device__ __align__(16) u16 d_wh[262144], d_wl[262144];       // [512][512] rows 0-255 Wg, 256-511 Wphi (x64)
__device__ __align__(16) u16 d_gh[33554432];                   // [n][l][a] fp16
__device__ __align__(16) u16 d_thh[16777216], d_thl[16777216]; // [n][c][m]
__device__ __align__(16) u16 d_pph[8388608], d_ppl[8388608];   // [n][a][m]
__device__ __align__(16) u16 d_ath[4194304];                   // [n][c][a] fp16

// ---------------- helpers ---------------------------------------------------
__device__ __forceinline__ u32 smem_u32(const void* p) {
    u32 a;
    asm("{ .reg .u64 t; cvta.to.shared.u64 t, %1; cvt.u32.u64 %0, t; }" : "=r"(a) : "l"(p));
    return a;
}
__device__ __forceinline__ void cpa(u32 d, const void* s) {
    asm volatile("cp.async.cg.shared.global [%0],[%1],16;" :: "r"(d), "l"(s));
}
#define CPC      asm volatile("cp.async.commit_group;" ::: "memory")
#define CP_WAIT1 asm volatile("cp.async.wait_group 1;" ::: "memory")
#define CP_WAIT0 asm volatile("cp.async.wait_group 0;" ::: "memory")

__device__ __forceinline__ void ldsm4(unsigned f[4], u32 a) {
    asm volatile("ldmatrix.sync.aligned.m8n8.x4.shared.b16 {%0,%1,%2,%3},[%4];"
                 : "=r"(f[0]), "=r"(f[1]), "=r"(f[2]), "=r"(f[3]) : "r"(a));
}
__device__ __forceinline__ void mma16816(float c[4], const unsigned a[4], unsigned b0, unsigned b1) {
    asm volatile("mma.sync.aligned.m16n8k16.row.col.f32.f16.f16.f32 "
                 "{%0,%1,%2,%3},{%4,%5,%6,%7},{%8,%9},{%0,%1,%2,%3};"
                 : "+f"(c[0]), "+f"(c[1]), "+f"(c[2]), "+f"(c[3])
                 : "r"(a[0]), "r"(a[1]), "r"(a[2]), "r"(a[3]), "r"(b0), "r"(b1));
}
__device__ __forceinline__ void hsplit(float v, u16& h, u16& l) {
    __half hh = __float2half_rn(v);
    h = __half_as_ushort(hh);
    l = __half_as_ushort(__float2half_rn(v - __half2float(hh)));
}
__device__ __forceinline__ u16 h1(float v) { return __half_as_ushort(__float2half_rn(v)); }

// ===========================================================================
// split_w: (Wg,Wphi)*64 -> fp16 hi/lo  [512][512]
// ===========================================================================
__global__ __launch_bounds__(256) void split_w_k(const float* __restrict__ wg,
                                                 const float* __restrict__ wp) {
    int idx = blockIdx.x * 256 + threadIdx.x;
    int r = idx >> 9, c = idx & 511;
    float v = ((r < 256) ? wg[r * 512 + c] : wp[(r - 256) * 512 + c]) * 64.0f;
    u16 h, l; hsplit(v, h, l);
    d_wh[idx] = h; d_wl[idx] = l;
}

// ===========================================================================
// pool_theta: 2x2 max of x -> fp16 hi/lo
// ===========================================================================
__global__ __launch_bounds__(256) void pool_theta_k(const float* __restrict__ x) {
    const size_t idx = (size_t)blockIdx.x * 256 + threadIdx.x;
    const int m = (int)(idx & 1023);
    const size_t nc = idx >> 10;
    const int r = m >> 5, w = m & 31;
    const float* p = x + nc * HWD + (size_t)(2 * r) * 64 + 2 * w;
    float v = fmaxf(fmaxf(p[0], p[1]), fmaxf(p[64], p[65]));
    u16 h, l; hsplit(v, h, l);
    d_thh[idx] = h; d_thl[idx] = l;
}

// ===========================================================================
// conv: G[l][a] fp16 (1-term), phi pooled hi/lo (3-term + fused pool)
// CTA 128l x 128a, 512 threads (16 warps, 2m x 8n, warp 64x16), K=512 BK=32.
// 80B-pitch tiles; buf: Xh 0, Xl 10240, Gh 20480, Ph 30720, Pl 40960
// ===========================================================================
#define CV_STG 51200
#define CV_SMEM (2 * CV_STG)
__global__ __launch_bounds__(512) void conv_mma(const float* __restrict__ x,
                                                const float* __restrict__ bg,
                                                const float* __restrict__ bp) {
    extern __shared__ char sm[];
    const u32 sb = smem_u32(sm);
    const int t = threadIdx.x, lane = t & 31, wp_ = t >> 5;
    const int wm = wp_ >> 3, wn = wp_ & 7;
    const int nb = blockIdx.z, a0 = blockIdx.y * 128, l0 = blockIdx.x * 128;
    const float* X = x + (size_t)nb * CCH * HWD;

    // hoisted fragment bases (80B pitch): addr = base + buf*CV_STG + ks*32
    const int hi16 = (lane >> 4) << 4;
    u32 xB[4], wB;
    #pragma unroll
    for (int mt = 0; mt < 4; ++mt)
        xB[mt] = sb + (u32)(wm * 64 + mt * 16 + (lane & 15)) * 80 + hi16;
    wB = sb + 20480 + (u32)(wn * 16 + (lane & 15)) * 80 + hi16;

    float aG[4][2][4] = {};
    float aP[4][2][4] = {};
    float xv0[4], xv1[4];

    {
        #pragma unroll
        for (int i = 0; i < 4; ++i) {
            int e = t + i * 512; int l = e & 127; int cp = e >> 7;
            xv0[i] = X[(size_t)(2 * cp) * HWD + l0 + l];
            xv1[i] = X[(size_t)(2 * cp + 1) * HWD + l0 + l];
        }
        {
            int row = t >> 2, ch = t & 3;
            u32 d = sb + row * 80 + (ch << 4);
            const size_t so = (size_t)row * 512 + ch * 8;
            cpa(d + 20480, d_wh + (size_t)a0 * 512 + so);
            cpa(d + 30720, d_wh + (size_t)(256 + a0) * 512 + so);
            cpa(d + 40960, d_wl + (size_t)(256 + a0) * 512 + so);
        }
        CPC;
        #pragma unroll
        for (int i = 0; i < 4; ++i) {
            int e = t + i * 512; int l = e & 127; int cp = e >> 7;
            u16 h0, q0, h1c, q1; hsplit(xv0[i], h0, q0); hsplit(xv1[i], h1c, q1);
            *(u32*)(sm + l * 80 + cp * 4) = (u32)h0 | ((u32)h1c << 16);
            *(u32*)(sm + 10240 + l * 80 + cp * 4) = (u32)q0 | ((u32)q1 << 16);
        }
    }

    #pragma unroll 1
    for (int s = 0; s < 16; ++s) {
        const int buf = s & 1;
        char* nbuf = sm + (buf ^ 1) * CV_STG;
        const u32 nbu = sb + (buf ^ 1) * CV_STG;
        if (s + 1 < 16) {
            const int k0 = (s + 1) * 32;
            #pragma unroll
            for (int i = 0; i < 4; ++i) {
                int e = t + i * 512; int l = e & 127; int cp = e >> 7;
                xv0[i] = X[(size_t)(k0 + 2 * cp) * HWD + l0 + l];
                xv1[i] = X[(size_t)(k0 + 2 * cp + 1) * HWD + l0 + l];
            }
            {
                int row = t >> 2, ch = t & 3;
                u32 d = nbu + row * 80 + (ch << 4);
                const size_t so = (size_t)row * 512 + ch * 8 + k0;
                cpa(d + 20480, d_wh + (size_t)a0 * 512 + so);
                cpa(d + 30720, d_wh + (size_t)(256 + a0) * 512 + so);
                cpa(d + 40960, d_wl + (size_t)(256 + a0) * 512 + so);
            }
            CPC; CP_WAIT1;
        } else { CP_WAIT0; }
        __syncthreads();

        const u32 bo = buf * CV_STG;
        #pragma unroll
        for (int ks = 0; ks < 2; ++ks) {
            const u32 ko = bo + ks * 32;
            unsigned ah[4][4], al[4][4], gh[4], ph[4], pl[4];
            #pragma unroll
            for (int mt = 0; mt < 4; ++mt) {
                ldsm4(ah[mt], xB[mt] + ko);
                ldsm4(al[mt], xB[mt] + 10240 + ko);
            }
            ldsm4(gh, wB + ko);
            ldsm4(ph, wB + 10240 + ko);
            ldsm4(pl, wB + 20480 + ko);
            // term-major: independent accumulator chains
            #pragma unroll
            for (int mt = 0; mt < 4; ++mt)
                #pragma unroll
                for (int n8 = 0; n8 < 2; ++n8) {
                    mma16816(aG[mt][n8], ah[mt], gh[n8], gh[2 + n8]);
                    mma16816(aP[mt][n8], ah[mt], ph[n8], ph[2 + n8]);
                }
            #pragma unroll
            for (int mt = 0; mt < 4; ++mt)
                #pragma unroll
                for (int n8 = 0; n8 < 2; ++n8)
                    mma16816(aP[mt][n8], al[mt], ph[n8], ph[2 + n8]);
            #pragma unroll
            for (int mt = 0; mt < 4; ++mt)
                #pragma unroll
                for (int n8 = 0; n8 < 2; ++n8)
                    mma16816(aP[mt][n8], ah[mt], pl[n8], pl[2 + n8]);
        }
        if (s + 1 < 16) {
            #pragma unroll
            for (int i = 0; i < 4; ++i) {
                int e = t + i * 512; int l = e & 127; int cp = e >> 7;
                u16 h0, q0, h1c, q1; hsplit(xv0[i], h0, q0); hsplit(xv1[i], h1c, q1);
                *(u32*)(nbuf + l * 80 + cp * 4) = (u32)h0 | ((u32)h1c << 16);
                *(u32*)(nbuf + 10240 + l * 80 + cp * 4) = (u32)q0 | ((u32)q1 << 16);
            }
        }
        __syncthreads();
    }

    // epilogue G (descale 1/64, +bias) -> d_gh [l][a]
    #pragma unroll
    for (int mt = 0; mt < 4; ++mt)
        #pragma unroll
        for (int n8 = 0; n8 < 2; ++n8) {
            const int l = l0 + wm * 64 + mt * 16 + (lane >> 2);
            const int a = a0 + wn * 16 + n8 * 8 + ((lane & 3) << 1);
            const float b0 = __ldg(bg + a), b1 = __ldg(bg + a + 1);
            const size_t i0 = ((size_t)nb * HWD + l) * AA + a;
            u16 g0 = h1(aG[mt][n8][0] * 0.015625f + b0);
            u16 g1 = h1(aG[mt][n8][1] * 0.015625f + b1);
            u16 g2 = h1(aG[mt][n8][2] * 0.015625f + b0);
            u16 g3 = h1(aG[mt][n8][3] * 0.015625f + b1);
            *(u32*)(d_gh + i0) = (u32)g0 | ((u32)g1 << 16);
            *(u32*)(d_gh + i0 + (size_t)8 * AA) = (u32)g2 | ((u32)g3 << 16);
        }

    // epilogue Phi: transpose to ts[a][132] fp32, fused 2x2 pool -> d_pp
    float* ts = (float*)sm;
    __syncthreads();
    #pragma unroll
    for (int mt = 0; mt < 4; ++mt)
        #pragma unroll
        for (int n8 = 0; n8 < 2; ++n8) {
            const int nl = wn * 16 + n8 * 8 + ((lane & 3) << 1);
            const int ml = wm * 64 + mt * 16 + (lane >> 2);
            const float b0 = __ldg(bp + a0 + nl), b1 = __ldg(bp + a0 + nl + 1);
            ts[nl * 132 + ml] = aP[mt][n8][0] * 0.015625f + b0;
            ts[(nl + 1) * 132 + ml] = aP[mt][n8][1] * 0.015625f + b1;
            ts[nl * 132 + ml + 8] = aP[mt][n8][2] * 0.015625f + b0;
            ts[(nl + 1) * 132 + ml + 8] = aP[mt][n8][3] * 0.015625f + b1;
        }
    __syncthreads();
    const int pb = l0 >> 7;
    #pragma unroll
    for (int i = 0; i < 8; ++i) {
        int e = t + i * 512; int a = e >> 5; int w = e & 31;
        float v = fmaxf(fmaxf(ts[a * 132 + 2 * w], ts[a * 132 + 2 * w + 1]),
                        fmaxf(ts[a * 132 + 64 + 2 * w], ts[a * 132 + 65 + 2 * w]));
        u16 h, l; hsplit(v, h, l);
        const size_t o = ((size_t)nb * AA + a0 + a) * PHW + pb * 32 + w;
        d_pph[o] = h; d_ppl[o] = l;
    }
}

// ===========================================================================
// cmat + fused softmax: theta . phi^T (3-term), row softmax, attn fp16.
// CTA 128c x 256a, 512 threads, K=1024 BK=64. 144B-pitch padded tiles.
// buf: Ah 0(18432), Al 18432, Bh 36864(36864), Bl 73728  (CM_STG=110592)
// ===========================================================================
#define CM_STG 110592
#define CM_SMEM (2 * CM_STG)
__global__ __launch_bounds__(512) void cmat_mma() {
    extern __shared__ char sm[];
    const u32 sb = smem_u32(sm);
    const int t = threadIdx.x, lane = t & 31, wp_ = t >> 5;
    const int wm = wp_ >> 3, wn = wp_ & 7;
    const int nb = blockIdx.y, c0 = blockIdx.x * 128;
    const u16* TH = d_thh + ((size_t)nb * CCH + c0) * PHW;
    const u16* TL = d_thl + ((size_t)nb * CCH + c0) * PHW;
    const u16* PH = d_pph + (size_t)nb * AA * PHW;
    const u16* PL = d_ppl + (size_t)nb * AA * PHW;

    const int hi16 = (lane >> 4) << 4;
    u32 aB[4], bB[2];
    #pragma unroll
    for (int mt = 0; mt < 4; ++mt)
        aB[mt] = sb + (u32)(wm * 64 + mt * 16 + (lane & 15)) * 144 + hi16;
    #pragma unroll
    for (int bt = 0; bt < 2; ++bt)
        bB[bt] = sb + 36864 + (u32)(wn * 32 + bt * 16 + (lane & 15)) * 144 + hi16;

    float acc[4][4][4] = {};

    // staging: 144B pitch
    #define STG_A(dst, src) do {                                                   \
        _Pragma("unroll")                                                          \
        for (int i_ = 0; i_ < 2; ++i_) {                                           \
            int idx_ = t + i_ * 512; int r_ = idx_ >> 3, ch_ = idx_ & 7;           \
            cpa((dst) + r_ * 144 + (ch_ << 4), (src) + (size_t)r_ * PHW + ch_ * 8);\
        } } while (0)
    #define STG_B(dst, src) do {                                                   \
        _Pragma("unroll")                                                          \
        for (int i_ = 0; i_ < 4; ++i_) {                                           \
            int idx_ = t + i_ * 512; int r_ = idx_ >> 3, ch_ = idx_ & 7;           \
            cpa((dst) + r_ * 144 + (ch_ << 4), (src) + (size_t)r_ * PHW + ch_ * 8);\
        } } while (0)

    STG_A(sb, TH); STG_A(sb + 18432, TL);
    STG_B(sb + 36864, PH); STG_B(sb + 73728, PL);
    CPC;
    #pragma unroll 1
    for (int s = 0; s < 16; ++s) {
        const int buf = s & 1;
        if (s + 1 < 16) {
            const u32 nbu = sb + (buf ^ 1) * CM_STG;
            const int k0 = (s + 1) * 64;
            STG_A(nbu, TH + k0); STG_A(nbu + 18432, TL + k0);
            STG_B(nbu + 36864, PH + k0); STG_B(nbu + 73728, PL + k0);
            CPC; CP_WAIT1;
        } else { CP_WAIT0; }
        __syncthreads();
        const u32 bo = buf * CM_STG;
        #pragma unroll
        for (int ks = 0; ks < 4; ++ks) {
            const u32 ko = bo + ks * 32;
            unsigned ah[4][4], al[4][4], bh[2][4], bl[2][4];
            #pragma unroll
            for (int mt = 0; mt < 4; ++mt) {
                ldsm4(ah[mt], aB[mt] + ko);
                ldsm4(al[mt], aB[mt] + 18432 + ko);
            }
            #pragma unroll
            for (int bt = 0; bt < 2; ++bt) {
                ldsm4(bh[bt], bB[bt] + ko);
                ldsm4(bl[bt], bB[bt] + 36864 + ko);
            }
            // term-major ordering
            #pragma unroll
            for (int mt = 0; mt < 4; ++mt)
                #pragma unroll
                for (int n8 = 0; n8 < 4; ++n8) {
                    const int bt = n8 >> 1, sl = n8 & 1;
                    mma16816(acc[mt][n8], ah[mt], bh[bt][sl], bh[bt][2 + sl]);
                }
            #pragma unroll
            for (int mt = 0; mt < 4; ++mt)
                #pragma unroll
                for (int n8 = 0; n8 < 4; ++n8) {
                    const int bt = n8 >> 1, sl = n8 & 1;
                    mma16816(acc[mt][n8], al[mt], bh[bt][sl], bh[bt][2 + sl]);
                }
            #pragma unroll
            for (int mt = 0; mt < 4; ++mt)
                #pragma unroll
                for (int n8 = 0; n8 < 4; ++n8) {
                    const int bt = n8 >> 1, sl = n8 & 1;
                    mma16816(acc[mt][n8], ah[mt], bl[bt][sl], bl[bt][2 + sl]);
                }
        }
        __syncthreads();
    }
    #undef STG_A
    #undef STG_B

    // ---- fused softmax over a=256 ----
    float* red = (float*)sm;
    const int rl = lane >> 2, l3 = lane & 3;
    float rmax[4][2], rinv[4][2];

    #pragma unroll
    for (int mt = 0; mt < 4; ++mt)
        #pragma unroll
        for (int rs = 0; rs < 2; ++rs) {
            float m = -3.0e38f;
            #pragma unroll
            for (int n8 = 0; n8 < 4; ++n8) {
                m = fmaxf(m, acc[mt][n8][rs * 2]);
                m = fmaxf(m, acc[mt][n8][rs * 2 + 1]);
            }
            m = fmaxf(m, __shfl_xor_sync(0xffffffffu, m, 1));
            m = fmaxf(m, __shfl_xor_sync(0xffffffffu, m, 2));
            if (l3 == 0) red[(((wm * 4 + mt) * 2 + rs) * 8 + rl) * 8 + wn] = m;
        }
    __syncthreads();
    #pragma unroll
    for (int mt = 0; mt < 4; ++mt)
        #pragma unroll
        for (int rs = 0; rs < 2; ++rs) {
            float m = -3.0e38f;
            #pragma unroll
            for (int w8 = 0; w8 < 8; ++w8)
                m = fmaxf(m, red[(((wm * 4 + mt) * 2 + rs) * 8 + rl) * 8 + w8]);
            rmax[mt][rs] = m;
        }
    __syncthreads();
    #pragma unroll
    for (int mt = 0; mt < 4; ++mt)
        #pragma unroll
        for (int rs = 0; rs < 2; ++rs) {
            float s = 0.f;
            #pragma unroll
            for (int n8 = 0; n8 < 4; ++n8) {
                float e0 = expf(acc[mt][n8][rs * 2] - rmax[mt][rs]);
                float e1 = expf(acc[mt][n8][rs * 2 + 1] - rmax[mt][rs]);
                acc[mt][n8][rs * 2] = e0; acc[mt][n8][rs * 2 + 1] = e1;
                s += e0 + e1;
            }
            s += __shfl_xor_sync(0xffffffffu, s, 1);
            s += __shfl_xor_sync(0xffffffffu, s, 2);
            if (l3 == 0) red[(((wm * 4 + mt) * 2 + rs) * 8 + rl) * 8 + wn] = s;
        }
    __syncthreads();
    #pragma unroll
    for (int mt = 0; mt < 4; ++mt)
        #pragma unroll
        for (int rs = 0; rs < 2; ++rs) {
            float s = 0.f;
            #pragma unroll
            for (int w8 = 0; w8 < 8; ++w8)
                s += red[(((wm * 4 + mt) * 2 + rs) * 8 + rl) * 8 + w8];
            rinv[mt][rs] = 1.0f / s;
        }

    #pragma unroll
    for (int mt = 0; mt < 4; ++mt)
        #pragma unroll
        for (int n8 = 0; n8 < 4; ++n8) {
            const int c = c0 + wm * 64 + mt * 16 + rl;
            const int a = wn * 32 + n8 * 8 + 2 * l3;
            size_t i0 = ((size_t)nb * CCH + c) * AA + a;
            u16 h0 = h1(acc[mt][n8][0] * rinv[mt][0]);
            u16 hh1 = h1(acc[mt][n8][1] * rinv[mt][0]);
            *(u32*)(d_ath + i0) = (u32)h0 | ((u32)hh1 << 16);
            i0 += (size_t)8 * AA;
            u16 h2 = h1(acc[mt][n8][2] * rinv[mt][1]);
            u16 h3 = h1(acc[mt][n8][3] * rinv[mt][1]);
            *(u32*)(d_ath + i0) = (u32)h2 | ((u32)h3 << 16);
        }
}

// ===========================================================================
// final: out[c][l] = attn_hi . G_hi + x  (1-term), K=256, BK=64
// 144B-pitch tiles; buf: AH 0(18432), BH 18432  (FN_STG=36864)
// ===========================================================================
#define FN_STG 36864
#define FN_SMEM (2 * FN_STG)
__global__ __launch_bounds__(256) void final_mma(const float* __restrict__ x,
                                                 float* __restrict__ out) {
    extern __shared__ char sm[];
    const u32 sb = smem_u32(sm);
    const int t = threadIdx.x, lane = t & 31;
    const int wm = (t >> 5) & 1, wn = t >> 6;
    const int nb = blockIdx.z, c0 = blockIdx.y * 128, l0 = blockIdx.x * 128;
    const u16* AH = d_ath + ((size_t)nb * CCH + c0) * AA;
    const u16* BH = d_gh + ((size_t)nb * HWD + l0) * AA;

    const int hi16 = (lane >> 4) << 4;
    u32 aB[4], bB[2];
    #pragma unroll
    for (int mt = 0; mt < 4; ++mt)
        aB[mt] = sb + (u32)(wm * 64 + mt * 16 + (lane & 15)) * 144 + hi16;
    #pragma unroll
    for (int bt = 0; bt < 2; ++bt)
        bB[bt] = sb + 18432 + (u32)(wn * 32 + bt * 16 + (lane & 15)) * 144 + hi16;

    float acc[4][4][4] = {};

    #define STG(dst, src) do {                                                     \
        _Pragma("unroll")                                                          \
        for (int i_ = 0; i_ < 4; ++i_) {                                           \
            int idx_ = t + i_ * 256; int r_ = idx_ >> 3, ch_ = idx_ & 7;           \
            cpa((dst) + r_ * 144 + (ch_ << 4), (src) + (size_t)r_ * AA + ch_ * 8); \
        } } while (0)

    STG(sb, AH); STG(sb + 18432, BH);
    CPC;
    #pragma unroll 1
    for (int s = 0; s < 4; ++s) {
        const int buf = s & 1;
        if (s + 1 < 4) {
            const u32 nbu = sb + (buf ^ 1) * FN_STG;
            const int k0 = (s + 1) * 64;
            STG(nbu, AH + k0); STG(nbu + 18432, BH + k0);
            CPC; CP_WAIT1;
        } else { CP_WAIT0; }
        __syncthreads();
        const u32 bo = buf * FN_STG;
        #pragma unroll
        for (int ks = 0; ks < 4; ++ks) {
            const u32 ko = bo + ks * 32;
            unsigned ah[4][4], bh[2][4];
            #pragma unroll
            for (int mt = 0; mt < 4; ++mt)
                ldsm4(ah[mt], aB[mt] + ko);
            #pragma unroll
            for (int bt = 0; bt < 2; ++bt)
                ldsm4(bh[bt], bB[bt] + ko);
            #pragma unroll
            for (int mt = 0; mt < 4; ++mt)
                #pragma unroll
                for (int n8 = 0; n8 < 4; ++n8) {
                    const int bt = n8 >> 1, sl = n8 & 1;
                    mma16816(acc[mt][n8], ah[mt], bh[bt][sl], bh[bt][2 + sl]);
                }
        }
        __syncthreads();
    }
    #undef STG

    #pragma unroll
    for (int mt = 0; mt < 4; ++mt)
        #pragma unroll
        for (int n8 = 0; n8 < 4; ++n8) {
            const int c = c0 + wm * 64 + mt * 16 + (lane >> 2);
            const int l = l0 + wn * 32 + n8 * 8 + ((lane & 3) << 1);
            size_t i0 = ((size_t)nb * CCH + c) * HWD + l;
            float2 xv = *(const float2*)(x + i0);
            float2 o0; o0.x = acc[mt][n8][0] + xv.x; o0.y = acc[mt][n8][1] + xv.y;
            *(float2*)(out + i0) = o0;
            i0 += (size_t)8 * HWD;
            float2 xw = *(const float2*)(x + i0);
            float2 o1; o1.x = acc[mt][n8][2] + xw.x; o1.y = acc[mt][n8][3] + xw.y;
            *(float2*)(out + i0) = o1;
        }
}

// ===========================================================================
extern "C" void kernel_launch(void* const* d_in, const int* in_sizes, int n_in,
                              void* d_out, int out_size) {
    (void)in_sizes; (void)n_in; (void)out_size;
    const float* x  = (const float*)d_in[0];
    const float* wg = (const float*)d_in[1];
    const float* bg = (const float*)d_in[2];
    const float* wp = (const float*)d_in[3];
    const float* bp = (const float*)d_in[4];
    float* out = (float*)d_out;

    cudaFuncSetAttribute(conv_mma,  cudaFuncAttributeMaxDynamicSharedMemorySize, CV_SMEM);
    cudaFuncSetAttribute(cmat_mma,  cudaFuncAttributeMaxDynamicSharedMemorySize, CM_SMEM);
    cudaFuncSetAttribute(final_mma, cudaFuncAttributeMaxDynamicSharedMemorySize, FN_SMEM);

    split_w_k<<<1024, 256>>>(wg, wp);
    pool_theta_k<<<65536, 256>>>(x);

    conv_mma<<<dim3(32, 2, NB), 512, CV_SMEM>>>(x, bg, bp);

    cmat_mma<<<dim3(4, NB), 512, CM_SMEM>>>();

    final_mma<<<dim3(32, 4, NB), 256, FN_SMEM>>>(x, out);
}

// round 10
// speedup vs baseline: 1.0535x; 1.0535x over previous
#include <cuda_runtime.h>
#include <cuda_fp16.h>
#include <cstdint>

#define NB 32
#define CCH 512
#define AA 256
#define HWD 4096
#define PHW 1024

typedef unsigned int u32;
typedef unsigned short u16;

// ---------------- scratch (static device globals) ---------------------------
__device__ __align__(16) u16 d_wh[262144], d_wl[262144];       // [512][512] rows 0-255 Wg, 256-511 Wphi (x64 scaled)
__device__ __align__(16) u16 d_gh[33554432];                   // [n][l][a] fp16 single
__device__ __align__(16) u16 d_thh[16777216], d_thl[16777216]; // [n][c][m]
__device__ __align__(16) u16 d_pph[8388608], d_ppl[8388608];   // [n][a][m]
__device__ __align__(16) u16 d_ath[4194304];                   // [n][c][a] fp16 single

// ---------------- helpers ---------------------------------------------------
__device__ __forceinline__ u32 smem_u32(const void* p) {
    u32 a;
    asm("{ .reg .u64 t; cvta.to.shared.u64 t, %1; cvt.u32.u64 %0, t; }" : "=r"(a) : "l"(p));
    return a;
}
__device__ __forceinline__ void cpa(u32 d, const void* s) {
    asm volatile("cp.async.cg.shared.global [%0],[%1],16;" :: "r"(d), "l"(s));
}
#define CPC      asm volatile("cp.async.commit_group;" ::: "memory")
#define CP_WAIT1 asm volatile("cp.async.wait_group 1;" ::: "memory")
#define CP_WAIT0 asm volatile("cp.async.wait_group 0;" ::: "memory")

__device__ __forceinline__ void ldsm4(unsigned f[4], u32 a) {
    asm volatile("ldmatrix.sync.aligned.m8n8.x4.shared.b16 {%0,%1,%2,%3},[%4];"
                 : "=r"(f[0]), "=r"(f[1]), "=r"(f[2]), "=r"(f[3]) : "r"(a));
}
__device__ __forceinline__ void mma16816(float c[4], const unsigned a[4], unsigned b0, unsigned b1) {
    asm volatile("mma.sync.aligned.m16n8k16.row.col.f32.f16.f16.f32 "
                 "{%0,%1,%2,%3},{%4,%5,%6,%7},{%8,%9},{%0,%1,%2,%3};"
                 : "+f"(c[0]), "+f"(c[1]), "+f"(c[2]), "+f"(c[3])
                 : "r"(a[0]), "r"(a[1]), "r"(a[2]), "r"(a[3]), "r"(b0), "r"(b1));
}
__device__ __forceinline__ void hsplit(float v, u16& h, u16& l) {
    __half hh = __float2half_rn(v);
    h = __half_as_ushort(hh);
    l = __half_as_ushort(__float2half_rn(v - __half2float(hh)));
}
__device__ __forceinline__ u16 h1(float v) { return __half_as_ushort(__float2half_rn(v)); }

// ldmatrix fragment from 128B-pitch SW128-swizzled K-major tile
__device__ __forceinline__ void ldA128(unsigned f[4], u32 tb, int r0, int k0, int lane) {
    int row = r0 + (lane & 15);
    int ch = (k0 >> 3) + (lane >> 4);
    ldsm4(f, tb + row * 128 + (((ch ^ (row & 7)) & 7) << 4));
}
// ldmatrix fragment from 80B-pitch (32-k) tile, no swizzle
__device__ __forceinline__ void ldA80(unsigned f[4], u32 tb, int r0, int k0, int lane) {
    int row = r0 + (lane & 15);
    int ch = (k0 >> 3) + (lane >> 4);
    ldsm4(f, tb + row * 80 + (ch << 4));
}
// cp.async stage of 128row x 32k fp16 tile (80B pitch), ld=512, 512 threads
__device__ __forceinline__ void stage80_512(u32 dst, const u16* src, int t) {
    int row = t >> 2, ch = t & 3;
    cpa(dst + row * 80 + (ch << 4), src + (size_t)row * 512 + ch * 8);
}

// ===========================================================================
// split_w: (Wg,Wphi)*64 -> fp16 hi/lo  [512][512]
// ===========================================================================
__global__ __launch_bounds__(256) void split_w_k(const float* __restrict__ wg,
                                                 const float* __restrict__ wp) {
    int idx = blockIdx.x * 256 + threadIdx.x;
    int r = idx >> 9, c = idx & 511;
    float v = ((r < 256) ? wg[r * 512 + c] : wp[(r - 256) * 512 + c]) * 64.0f;
    u16 h, l; hsplit(v, h, l);
    d_wh[idx] = h; d_wl[idx] = l;
}

// ===========================================================================
// pool_theta: 2x2 max of x -> fp16 hi/lo
// ===========================================================================
__global__ __launch_bounds__(256) void pool_theta_k(const float* __restrict__ x) {
    const size_t idx = (size_t)blockIdx.x * 256 + threadIdx.x;
    const int m = (int)(idx & 1023);
    const size_t nc = idx >> 10;
    const int r = m >> 5, w = m & 31;
    const float* p = x + nc * HWD + (size_t)(2 * r) * 64 + 2 * w;
    float v = fmaxf(fmaxf(p[0], p[1]), fmaxf(p[64], p[65]));
    u16 h, l; hsplit(v, h, l);
    d_thh[idx] = h; d_thl[idx] = l;
}

// ===========================================================================
// conv: G[l][a] fp16 (1-term), phi pooled fp16 hi/lo (3-term + fused 2x2 pool)
// CTA 128l x 128a, 512 threads (16 warps, 2m x 8n, warp 64x16), K=512 BK=32.
// buf: Xh 0, Xl 10240, Gh 20480, Ph 30720, Pl 40960   (CV_STG=51200)
// ===========================================================================
#define CV_STG 51200
#define CV_SMEM (2 * CV_STG)
__global__ __launch_bounds__(512) void conv_mma(const float* __restrict__ x,
                                                const float* __restrict__ bg,
                                                const float* __restrict__ bp) {
    extern __shared__ char sm[];
    const u32 sb = smem_u32(sm);
    const int t = threadIdx.x, lane = t & 31, wp_ = t >> 5;
    const int wm = wp_ >> 3, wn = wp_ & 7;
    const int nb = blockIdx.z, a0 = blockIdx.y * 128, l0 = blockIdx.x * 128;
    const float* X = x + (size_t)nb * CCH * HWD;

    float aG[4][2][4] = {};
    float aP[4][2][4] = {};
    float xv0[4], xv1[4];

    {
        #pragma unroll
        for (int i = 0; i < 4; ++i) {
            int e = t + i * 512; int l = e & 127; int cp = e >> 7;
            xv0[i] = X[(size_t)(2 * cp) * HWD + l0 + l];
            xv1[i] = X[(size_t)(2 * cp + 1) * HWD + l0 + l];
        }
        stage80_512(sb + 20480, d_wh + (size_t)a0 * 512, t);
        stage80_512(sb + 30720, d_wh + (size_t)(256 + a0) * 512, t);
        stage80_512(sb + 40960, d_wl + (size_t)(256 + a0) * 512, t);
        CPC;
        #pragma unroll
        for (int i = 0; i < 4; ++i) {
            int e = t + i * 512; int l = e & 127; int cp = e >> 7;
            u16 h0, q0, h1c, q1; hsplit(xv0[i], h0, q0); hsplit(xv1[i], h1c, q1);
            *(u32*)(sm + l * 80 + cp * 4) = (u32)h0 | ((u32)h1c << 16);
            *(u32*)(sm + 10240 + l * 80 + cp * 4) = (u32)q0 | ((u32)q1 << 16);
        }
    }

    #pragma unroll 1
    for (int s = 0; s < 16; ++s) {
        const int buf = s & 1;
        char* nbuf = sm + (buf ^ 1) * CV_STG;
        const u32 nbu = sb + (buf ^ 1) * CV_STG;
        if (s + 1 < 16) {
            const int k0 = (s + 1) * 32;
            #pragma unroll
            for (int i = 0; i < 4; ++i) {
                int e = t + i * 512; int l = e & 127; int cp = e >> 7;
                xv0[i] = X[(size_t)(k0 + 2 * cp) * HWD + l0 + l];
                xv1[i] = X[(size_t)(k0 + 2 * cp + 1) * HWD + l0 + l];
            }
            stage80_512(nbu + 20480, d_wh + (size_t)a0 * 512 + k0, t);
            stage80_512(nbu + 30720, d_wh + (size_t)(256 + a0) * 512 + k0, t);
            stage80_512(nbu + 40960, d_wl + (size_t)(256 + a0) * 512 + k0, t);
            CPC; CP_WAIT1;
        } else { CP_WAIT0; }
        __syncthreads();

        const u32 bu = sb + buf * CV_STG;
        #pragma unroll
        for (int ks = 0; ks < 2; ++ks) {
            const int k0 = ks * 16;
            unsigned ah[4][4], al[4][4];
            #pragma unroll
            for (int mt = 0; mt < 4; ++mt) {
                ldA80(ah[mt], bu, wm * 64 + mt * 16, k0, lane);
                ldA80(al[mt], bu + 10240, wm * 64 + mt * 16, k0, lane);
            }
            unsigned gh[4], ph[4], pl[4];
            ldA80(gh, bu + 20480, wn * 16, k0, lane);
            ldA80(ph, bu + 30720, wn * 16, k0, lane);
            ldA80(pl, bu + 40960, wn * 16, k0, lane);
            #pragma unroll
            for (int mt = 0; mt < 4; ++mt)
                #pragma unroll
                for (int n8 = 0; n8 < 2; ++n8) {
                    mma16816(aG[mt][n8], ah[mt], gh[n8], gh[2 + n8]);
                    mma16816(aP[mt][n8], ah[mt], ph[n8], ph[2 + n8]);
                    mma16816(aP[mt][n8], al[mt], ph[n8], ph[2 + n8]);
                    mma16816(aP[mt][n8], ah[mt], pl[n8], pl[2 + n8]);
                }
        }
        if (s + 1 < 16) {
            #pragma unroll
            for (int i = 0; i < 4; ++i) {
                int e = t + i * 512; int l = e & 127; int cp = e >> 7;
                u16 h0, q0, h1c, q1; hsplit(xv0[i], h0, q0); hsplit(xv1[i], h1c, q1);
                *(u32*)(nbuf + l * 80 + cp * 4) = (u32)h0 | ((u32)h1c << 16);
                *(u32*)(nbuf + 10240 + l * 80 + cp * 4) = (u32)q0 | ((u32)q1 << 16);
            }
        }
        __syncthreads();
    }

    // epilogue G (descale 1/64, +bias) -> d_gh [l][a] fp16 single
    #pragma unroll
    for (int mt = 0; mt < 4; ++mt)
        #pragma unroll
        for (int n8 = 0; n8 < 2; ++n8) {
            const int l = l0 + wm * 64 + mt * 16 + (lane >> 2);
            const int a = a0 + wn * 16 + n8 * 8 + ((lane & 3) << 1);
            const float b0 = __ldg(bg + a), b1 = __ldg(bg + a + 1);
            const size_t i0 = ((size_t)nb * HWD + l) * AA + a;
            u16 g0 = h1(aG[mt][n8][0] * 0.015625f + b0);
            u16 g1 = h1(aG[mt][n8][1] * 0.015625f + b1);
            u16 g2 = h1(aG[mt][n8][2] * 0.015625f + b0);
            u16 g3 = h1(aG[mt][n8][3] * 0.015625f + b1);
            *(u32*)(d_gh + i0) = (u32)g0 | ((u32)g1 << 16);
            *(u32*)(d_gh + i0 + (size_t)8 * AA) = (u32)g2 | ((u32)g3 << 16);
        }

    // epilogue Phi: transpose to ts[a][132] fp32, then fused 2x2 pool -> d_pp
    float* ts = (float*)sm;
    __syncthreads();
    #pragma unroll
    for (int mt = 0; mt < 4; ++mt)
        #pragma unroll
        for (int n8 = 0; n8 < 2; ++n8) {
            const int nl = wn * 16 + n8 * 8 + ((lane & 3) << 1);
            const int ml = wm * 64 + mt * 16 + (lane >> 2);
            const float b0 = __ldg(bp + a0 + nl), b1 = __ldg(bp + a0 + nl + 1);
            ts[nl * 132 + ml] = aP[mt][n8][0] * 0.015625f + b0;
            ts[(nl + 1) * 132 + ml] = aP[mt][n8][1] * 0.015625f + b1;
            ts[nl * 132 + ml + 8] = aP[mt][n8][2] * 0.015625f + b0;
            ts[(nl + 1) * 132 + ml + 8] = aP[mt][n8][3] * 0.015625f + b1;
        }
    __syncthreads();
    const int pb = l0 >> 7;
    #pragma unroll
    for (int i = 0; i < 8; ++i) {
        int e = t + i * 512; int a = e >> 5; int w = e & 31;
        float v = fmaxf(fmaxf(ts[a * 132 + 2 * w], ts[a * 132 + 2 * w + 1]),
                        fmaxf(ts[a * 132 + 64 + 2 * w], ts[a * 132 + 65 + 2 * w]));
        u16 h, l; hsplit(v, h, l);
        const size_t o = ((size_t)nb * AA + a0 + a) * PHW + pb * 32 + w;
        d_pph[o] = h; d_ppl[o] = l;
    }
}

// ===========================================================================
// cmat + fused softmax: theta . phi^T (3-term), row softmax, attn fp16 single.
// CTA 128c x 256a full row, 512 threads, K=1024 BK=64.
// buf: Ah 0(16K), Al 16384, Bh 32768(32K), Bl 65536(32K)  (CM_STG=98304)
// ===========================================================================
#define CM_STG 98304
#define CM_SMEM (2 * CM_STG)
__global__ __launch_bounds__(512) void cmat_mma() {
    extern __shared__ char sm[];
    const u32 sb = smem_u32(sm);
    const int t = threadIdx.x, lane = t & 31, wp_ = t >> 5;
    const int wm = wp_ >> 3, wn = wp_ & 7;
    const int nb = blockIdx.y, c0 = blockIdx.x * 128;
    const u16* TH = d_thh + ((size_t)nb * CCH + c0) * PHW;
    const u16* TL = d_thl + ((size_t)nb * CCH + c0) * PHW;
    const u16* PH = d_pph + (size_t)nb * AA * PHW;
    const u16* PL = d_ppl + (size_t)nb * AA * PHW;

    float acc[4][4][4] = {};

    #define STG_A(dst, src) do {                                                   \
        _Pragma("unroll")                                                          \
        for (int i_ = 0; i_ < 2; ++i_) {                                           \
            int idx_ = t + i_ * 512; int r_ = idx_ >> 3, ch_ = idx_ & 7;           \
            cpa((dst) + r_ * 128 + (((ch_ ^ (r_ & 7)) & 7) << 4),                  \
                (src) + (size_t)r_ * PHW + ch_ * 8);                               \
        } } while (0)
    #define STG_B(dst, src) do {                                                   \
        _Pragma("unroll")                                                          \
        for (int i_ = 0; i_ < 4; ++i_) {                                           \
            int idx_ = t + i_ * 512; int r_ = idx_ >> 3, ch_ = idx_ & 7;           \
            cpa((dst) + r_ * 128 + (((ch_ ^ (r_ & 7)) & 7) << 4),                  \
                (src) + (size_t)r_ * PHW + ch_ * 8);                               \
        } } while (0)

    STG_A(sb, TH); STG_A(sb + 16384, TL);
    STG_B(sb + 32768, PH); STG_B(sb + 65536, PL);
    CPC;
    #pragma unroll 1
    for (int s = 0; s < 16; ++s) {
        const int buf = s & 1;
        if (s + 1 < 16) {
            const u32 nbu = sb + (buf ^ 1) * CM_STG;
            const int k0 = (s + 1) * 64;
            STG_A(nbu, TH + k0); STG_A(nbu + 16384, TL + k0);
            STG_B(nbu + 32768, PH + k0); STG_B(nbu + 65536, PL + k0);
            CPC; CP_WAIT1;
        } else { CP_WAIT0; }
        __syncthreads();
        const u32 bu = sb + buf * CM_STG;
        #pragma unroll
        for (int ks = 0; ks < 4; ++ks) {
            const int k0 = ks * 16;
            unsigned ah[4][4], al[4][4], bh[2][4], bl[2][4];
            #pragma unroll
            for (int mt = 0; mt < 4; ++mt) {
                ldA128(ah[mt], bu, wm * 64 + mt * 16, k0, lane);
                ldA128(al[mt], bu + 16384, wm * 64 + mt * 16, k0, lane);
            }
            #pragma unroll
            for (int bt = 0; bt < 2; ++bt) {
                ldA128(bh[bt], bu + 32768, wn * 32 + bt * 16, k0, lane);
                ldA128(bl[bt], bu + 65536, wn * 32 + bt * 16, k0, lane);
            }
            #pragma unroll
            for (int mt = 0; mt < 4; ++mt)
                #pragma unroll
                for (int n8 = 0; n8 < 4; ++n8) {
                    const int bt = n8 >> 1, sl = n8 & 1;
                    mma16816(acc[mt][n8], ah[mt], bh[bt][sl], bh[bt][2 + sl]);
                    mma16816(acc[mt][n8], al[mt], bh[bt][sl], bh[bt][2 + sl]);
                    mma16816(acc[mt][n8], ah[mt], bl[bt][sl], bl[bt][2 + sl]);
                }
        }
        __syncthreads();
    }
    #undef STG_A
    #undef STG_B

    // ---- fused softmax over a=256 ----
    float* red = (float*)sm;
    const int rl = lane >> 2, l3 = lane & 3;
    float rmax[4][2], rinv[4][2];

    #pragma unroll
    for (int mt = 0; mt < 4; ++mt)
        #pragma unroll
        for (int rs = 0; rs < 2; ++rs) {
            float m = -3.0e38f;
            #pragma unroll
            for (int n8 = 0; n8 < 4; ++n8) {
                m = fmaxf(m, acc[mt][n8][rs * 2]);
                m = fmaxf(m, acc[mt][n8][rs * 2 + 1]);
            }
            m = fmaxf(m, __shfl_xor_sync(0xffffffffu, m, 1));
            m = fmaxf(m, __shfl_xor_sync(0xffffffffu, m, 2));
            if (l3 == 0) red[(((wm * 4 + mt) * 2 + rs) * 8 + rl) * 8 + wn] = m;
        }
    __syncthreads();
    #pragma unroll
    for (int mt = 0; mt < 4; ++mt)
        #pragma unroll
        for (int rs = 0; rs < 2; ++rs) {
            float m = -3.0e38f;
            #pragma unroll
            for (int w8 = 0; w8 < 8; ++w8)
                m = fmaxf(m, red[(((wm * 4 + mt) * 2 + rs) * 8 + rl) * 8 + w8]);
            rmax[mt][rs] = m;
        }
    __syncthreads();
    #pragma unroll
    for (int mt = 0; mt < 4; ++mt)
        #pragma unroll
        for (int rs = 0; rs < 2; ++rs) {
            float s = 0.f;
            #pragma unroll
            for (int n8 = 0; n8 < 4; ++n8) {
                float e0 = expf(acc[mt][n8][rs * 2] - rmax[mt][rs]);
                float e1 = expf(acc[mt][n8][rs * 2 + 1] - rmax[mt][rs]);
                acc[mt][n8][rs * 2] = e0; acc[mt][n8][rs * 2 + 1] = e1;
                s += e0 + e1;
            }
            s += __shfl_xor_sync(0xffffffffu, s, 1);
            s += __shfl_xor_sync(0xffffffffu, s, 2);
            if (l3 == 0) red[(((wm * 4 + mt) * 2 + rs) * 8 + rl) * 8 + wn] = s;
        }
    __syncthreads();
    #pragma unroll
    for (int mt = 0; mt < 4; ++mt)
        #pragma unroll
        for (int rs = 0; rs < 2; ++rs) {
            float s = 0.f;
            #pragma unroll
            for (int w8 = 0; w8 < 8; ++w8)
                s += red[(((wm * 4 + mt) * 2 + rs) * 8 + rl) * 8 + w8];
            rinv[mt][rs] = 1.0f / s;
        }

    #pragma unroll
    for (int mt = 0; mt < 4; ++mt)
        #pragma unroll
        for (int n8 = 0; n8 < 4; ++n8) {
            const int c = c0 + wm * 64 + mt * 16 + rl;
            const int a = wn * 32 + n8 * 8 + 2 * l3;
            size_t i0 = ((size_t)nb * CCH + c) * AA + a;
            u16 h0 = h1(acc[mt][n8][0] * rinv[mt][0]);
            u16 hh1 = h1(acc[mt][n8][1] * rinv[mt][0]);
            *(u32*)(d_ath + i0) = (u32)h0 | ((u32)hh1 << 16);
            i0 += (size_t)8 * AA;
            u16 h2 = h1(acc[mt][n8][2] * rinv[mt][1]);
            u16 h3 = h1(acc[mt][n8][3] * rinv[mt][1]);
            *(u32*)(d_ath + i0) = (u32)h2 | ((u32)h3 << 16);
        }
}

// ===========================================================================
// final: out[c][l] = attn_hi . G_hi + x  (1-term), K=256, BK=64
// buf: AH 0(16K), BH 16384(16K)  (FN_STG=32768)
// ===========================================================================
#define FN_STG 32768
#define FN_SMEM (2 * FN_STG)
__global__ __launch_bounds__(256) void final_mma(const float* __restrict__ x,
                                                 float* __restrict__ out) {
    extern __shared__ char sm[];
    const u32 sb = smem_u32(sm);
    const int t = threadIdx.x, lane = t & 31;
    const int wm = (t >> 5) & 1, wn = t >> 6;
    const int nb = blockIdx.z, c0 = blockIdx.y * 128, l0 = blockIdx.x * 128;
    const u16* AH = d_ath + ((size_t)nb * CCH + c0) * AA;
    const u16* BH = d_gh + ((size_t)nb * HWD + l0) * AA;

    float acc[4][4][4] = {};

    #define STG(dst, src) do {                                                     \
        _Pragma("unroll")                                                          \
        for (int i_ = 0; i_ < 4; ++i_) {                                           \
            int idx_ = t + i_ * 256; int r_ = idx_ >> 3, ch_ = idx_ & 7;           \
            cpa((dst) + r_ * 128 + (((ch_ ^ (r_ & 7)) & 7) << 4),                  \
                (src) + (size_t)r_ * AA + ch_ * 8);                                \
        } } while (0)

    STG(sb, AH); STG(sb + 16384, BH);
    CPC;
    #pragma unroll 1
    for (int s = 0; s < 4; ++s) {
        const int buf = s & 1;
        if (s + 1 < 4) {
            const u32 nbu = sb + (buf ^ 1) * FN_STG;
            const int k0 = (s + 1) * 64;
            STG(nbu, AH + k0); STG(nbu + 16384, BH + k0);
            CPC; CP_WAIT1;
        } else { CP_WAIT0; }
        __syncthreads();
        const u32 bu = sb + buf * FN_STG;
        #pragma unroll
        for (int ks = 0; ks < 4; ++ks) {
            const int k0 = ks * 16;
            unsigned ah[4][4], bh[2][4];
            #pragma unroll
            for (int mt = 0; mt < 4; ++mt)
                ldA128(ah[mt], bu, wm * 64 + mt * 16, k0, lane);
            #pragma unroll
            for (int bt = 0; bt < 2; ++bt)
                ldA128(bh[bt], bu + 16384, wn * 32 + bt * 16, k0, lane);
            #pragma unroll
            for (int mt = 0; mt < 4; ++mt)
                #pragma unroll
                for (int n8 = 0; n8 < 4; ++n8) {
                    const int bt = n8 >> 1, sl = n8 & 1;
                    mma16816(acc[mt][n8], ah[mt], bh[bt][sl], bh[bt][2 + sl]);
                }
        }
        __syncthreads();
    }
    #undef STG

    #pragma unroll
    for (int mt = 0; mt < 4; ++mt)
        #pragma unroll
        for (int n8 = 0; n8 < 4; ++n8) {
            const int c = c0 + wm * 64 + mt * 16 + (lane >> 2);
            const int l = l0 + wn * 32 + n8 * 8 + ((lane & 3) << 1);
            size_t i0 = ((size_t)nb * CCH + c) * HWD + l;
            float2 xv = *(const float2*)(x + i0);
            float2 o0; o0.x = acc[mt][n8][0] + xv.x; o0.y = acc[mt][n8][1] + xv.y;
            *(float2*)(out + i0) = o0;
            i0 += (size_t)8 * HWD;
            float2 xw = *(const float2*)(x + i0);
            float2 o1; o1.x = acc[mt][n8][2] + xw.x; o1.y = acc[mt][n8][3] + xw.y;
            *(float2*)(out + i0) = o1;
        }
}

// ===========================================================================
// launch: fork pool_theta onto a side stream, overlapped with split_w + conv.
// Stream/event created per call (kernel_launch runs only a few times; no
// device-memory allocation involved). Join before cmat.
// ===========================================================================
extern "C" void kernel_launch(void* const* d_in, const int* in_sizes, int n_in,
                              void* d_out, int out_size) {
    (void)in_sizes; (void)n_in; (void)out_size;
    const float* x  = (const float*)d_in[0];
    const float* wg = (const float*)d_in[1];
    const float* bg = (const float*)d_in[2];
    const float* wp = (const float*)d_in[3];
    const float* bp = (const float*)d_in[4];
    float* out = (float*)d_out;

    cudaFuncSetAttribute(conv_mma,  cudaFuncAttributeMaxDynamicSharedMemorySize, CV_SMEM);
    cudaFuncSetAttribute(cmat_mma,  cudaFuncAttributeMaxDynamicSharedMemorySize, CM_SMEM);
    cudaFuncSetAttribute(final_mma, cudaFuncAttributeMaxDynamicSharedMemorySize, FN_SMEM);

    cudaStream_t s2;
    cudaEvent_t eFork, eJoin;
    cudaStreamCreateWithFlags(&s2, cudaStreamNonBlocking);
    cudaEventCreateWithFlags(&eFork, cudaEventDisableTiming);
    cudaEventCreateWithFlags(&eJoin, cudaEventDisableTiming);

    // fork point on the main (capture-origin) stream
    cudaEventRecord(eFork, 0);
    cudaStreamWaitEvent(s2, eFork, 0);

    // side stream: theta pooling (independent of W/conv)
    pool_theta_k<<<65536, 256, 0, s2>>>(x);
    cudaEventRecord(eJoin, s2);

    // main stream: W split -> conv (conv depends on split_w only)
    split_w_k<<<1024, 256>>>(wg, wp);
    conv_mma<<<dim3(32, 2, NB), 512, CV_SMEM>>>(x, bg, bp);

    // join before cmat (needs theta + phi pools)
    cudaStreamWaitEvent(0, eJoin, 0);

    cmat_mma<<<dim3(4, NB), 512, CM_SMEM>>>();
    final_mma<<<dim3(32, 4, NB), 256, FN_SMEM>>>(x, out);
}